// round 16
// baseline (speedup 1.0000x reference)
#include <cuda_runtime.h>
#include <cuda_fp16.h>
#include <cstdint>

#define BB 128
#define TT 2048
#define DD 64
#define HH 128
#define OO 32
#define NCHUNK 16            // 2048 / 128 t-chunks

typedef unsigned long long ull;

// Scratch (allocation-free rule: __device__ globals)
__device__ float g_xp0[(size_t)BB * TT * HH];  // layer0 input projection
__device__ float g_h1[(size_t)BB * TT * HH];   // layer1 hidden states
__device__ int   g_scanflag[BB];               // scan-done flags
__device__ int   g_xpflag[NCHUNK * BB];        // xp chunk-ready flags [c*BB+b]

// ---------------------------------------------------------------------------
__device__ __forceinline__ float tanh_mufu(float x) {
    float t;
    asm("tanh.approx.f32 %0, %1;" : "=f"(t) : "f"(x));
    return t;
}

// Half-row fp16 dot (64 of 128 elements), interleaved 16B blocks: thread-half
// h covers blocks {2j+h : j=0..7} (8 halves each). A warp reads only 2
// distinct 16B lines per j -> conflict-free broadcast. 8 chains of depth 4.
__device__ __forceinline__ float dot64h(const __half2* w2, const __half* v, int h) {
    __half2 acc[8];
#pragma unroll
    for (int i = 0; i < 8; i++) acc[i] = __float2half2_rn(0.f);
    const uint4* v16 = (const uint4*)v;
#pragma unroll
    for (int j = 0; j < 8; j++) {
        uint4 p = v16[2 * j + h];
        __half2 pv0 = *(const __half2*)&p.x;
        __half2 pv1 = *(const __half2*)&p.y;
        __half2 pv2 = *(const __half2*)&p.z;
        __half2 pv3 = *(const __half2*)&p.w;
        int c = (j & 1) * 4;
        acc[c + 0] = __hfma2(w2[4 * j + 0], pv0, acc[c + 0]);
        acc[c + 1] = __hfma2(w2[4 * j + 1], pv1, acc[c + 1]);
        acc[c + 2] = __hfma2(w2[4 * j + 2], pv2, acc[c + 2]);
        acc[c + 3] = __hfma2(w2[4 * j + 3], pv3, acc[c + 3]);
    }
    float2 f0 = __half22float2(acc[0]);
    float2 f1 = __half22float2(acc[1]);
    float2 f2 = __half22float2(acc[2]);
    float2 f3 = __half22float2(acc[3]);
    float2 f4 = __half22float2(acc[4]);
    float2 f5 = __half22float2(acc[5]);
    float2 f6 = __half22float2(acc[6]);
    float2 f7 = __half22float2(acc[7]);
    float p0 = (f0.x + f0.y) + (f1.x + f1.y);
    float p1 = (f2.x + f2.y) + (f3.x + f3.y);
    float p2 = (f4.x + f4.y) + (f5.x + f5.y);
    float p3 = (f6.x + f6.y) + (f7.x + f7.y);
    return (p0 + p1) + (p2 + p3);
}

__device__ __forceinline__ void spin_acq(const int* p) {
    int v;
    while (true) {
        asm volatile("ld.acquire.gpu.global.b32 %0, [%1];" : "=r"(v) : "l"(p) : "memory");
        if (v) break;
        __nanosleep(100);
    }
}

// ---------------------------------------------------------------------------
__global__ void init_kernel() {
    int tid = threadIdx.x;
    for (int i = tid; i < NCHUNK * BB; i += 256) g_xpflag[i] = 0;
    if (tid < BB) g_scanflag[tid] = 0;
}

// ---------------------------------------------------------------------------
// MERGED kernel: xproj + scan + fc, 768 threads.
//   blocks [0,128)      : scan role, SPLIT-ROW: 3 groups x 256 thr, 2 thr/row
//   blocks [128,2176)   : xproj role (512 active thr, 8x4 tiles), chunk-major
//   blocks [2176,10368) : fc role, reverse batch order
#define XPAD 132
__global__ void __launch_bounds__(768, 1)
mega_kernel(const float* __restrict__ x,
            const float* __restrict__ Wih0, const float* __restrict__ bih0,
            const float* __restrict__ bhh0,
            const float* __restrict__ Whh0, const float* __restrict__ Wih1,
            const float* __restrict__ Whh1, const float* __restrict__ bih1,
            const float* __restrict__ bhh1, const int* __restrict__ lengths,
            const float* __restrict__ Wfc,  const float* __restrict__ bfc,
            float* __restrict__ out) {
    int tid = threadIdx.x;

    if (blockIdx.x < BB) {
        // --------------------- scan role (fp16, split-row) ---------------------
        __shared__ __align__(16) __half h0buf[2][HH];
        __shared__ __align__(16) __half h1buf[2][HH];
        __shared__ __align__(16) float  p1buf[2][HH];

        int b   = blockIdx.x;
        int L   = lengths[b];
        int grp = tid >> 8;          // 0,1,2 (256 threads each)
        int rh  = tid & 255;
        int row = rh >> 1;
        int h   = rh & 1;            // row half; halves on adjacent lanes
        bool isg0 = (grp == 0), isg1 = (grp == 1), isg2 = (grp == 2);
        bool h0t  = (h == 0);

        const float* Wrow = (isg0 ? Whh0 : (isg1 ? Wih1 : Whh1)) + (size_t)row * HH;
        __half2 w2[32];
#pragma unroll
        for (int jj = 0; jj < 8; jj++) {
            int bl = 2 * jj + h;
#pragma unroll
            for (int k = 0; k < 4; k++) {
                float2 t = ((const float2*)Wrow)[4 * bl + k];
                w2[4 * jj + k] = __floats2half2_rn(t.x, t.y);
            }
        }

        const float* xp_base = g_xp0 + (size_t)b * TT * HH + row;
        if (isg0 && h0t) spin_acq(&g_xpflag[b]);   // chunk 0 ready
        float xp[4];
#pragma unroll
        for (int i = 0; i < 4; i++) {
            float v = 0.f;
            if (isg0 && h0t) v = xp_base[(size_t)i * HH];
            else if (isg1 && h0t) v = bih1[row] + bhh1[row];
            xp[i] = v;
        }

        if (isg0 && h0t) h0buf[1][row] = __float2half_rn(0.f); // value -1
        if (isg2 && h0t) h1buf[1][row] = __float2half_rn(0.f);

        const __half* vrd[2];
        const float*  prd[2];
        __half* sth[2];
        float*  stf[2];
#pragma unroll
        for (int pa = 0; pa < 2; pa++) {
            int pb = pa ^ 1;
            vrd[pa] = isg2 ? h1buf[pb] : h0buf[pb];
            prd[pa] = &p1buf[pa][row];
            sth[pa] = isg0 ? &h0buf[pa][row] : &h1buf[pa][row];
            stf[pa] = &p1buf[pb][row];
        }
        float* h1out = g_h1 + (size_t)b * TT * HH + row;

        __syncthreads();

        int spad = ((L + 2) + 3) & ~3;
        for (int s0 = 0; s0 < spad; s0 += 4) {
            if (((s0 & 127) == 124) && isg0 && h0t) {   // prefetch crosses chunk
                int c = (s0 + 7) >> 7; if (c > NCHUNK - 1) c = NCHUNK - 1;
                spin_acq(&g_xpflag[c * BB + b]);
            }
#pragma unroll
            for (int u = 0; u < 4; u++) {
                int s  = s0 + u;
                int pa = u & 1;
                float extra = *prd[pa];                 // p1 value s-2 (g2 only)
                float part  = dot64h(w2, vrd[pa], h);
                part += __shfl_xor_sync(0xffffffffu, part, 1);  // cross-half
                float pre = part + xp[u] + (isg2 ? extra : 0.f);
                float th  = tanh_mufu(pre);
                if (h0t) {
                    if (isg1) *stf[pa] = pre;                       // p1 (fp32)
                    else if (!isg2 || s >= 2)
                        *sth[pa] = __float2half_rn(th);             // h0/h1
                    if (isg2 && (unsigned)(s - 2) < (unsigned)TT)
                        h1out[(size_t)(s - 2) * HH] = th;           // fp32 for fc
                    if (isg0) {                                     // prefetch
                        int nidx = s + 4; if (nidx > TT - 1) nidx = TT - 1;
                        xp[u] = __ldg(&xp_base[(size_t)nidx * HH]);
                    }
                }
                __syncthreads();
            }
        }

        __threadfence();
        __syncthreads();
        if (tid == 0)
            asm volatile("st.release.gpu.global.b32 [%0], %1;"
                         :: "l"(&g_scanflag[b]), "r"(1) : "memory");
    } else if (blockIdx.x < BB + NCHUNK * BB) {
        // ------------------------ xproj role (8x4 tiles) -------------------------
        extern __shared__ float sm[];
        float* xsT = sm;                 // [64][XPAD]
        float* wsT = sm + 64 * XPAD;     // [64][XPAD]
        int f    = blockIdx.x - BB;
        int c    = f >> 7;               // t-chunk (chunk-major order)
        int b    = f & 127;
        int row0 = b * TT + c * 128;     // 128 contiguous (b,t) rows

        if (tid < 512) {
            const float4* xg = (const float4*)(x + (size_t)row0 * DD);
#pragma unroll
            for (int j = 0; j < 4; j++) {
                int idx = tid + 512 * j;            // 2048 float4
                float4 v = xg[idx];
                int r = idx >> 4, d4 = (idx & 15) << 2;
                xsT[(d4 + 0) * XPAD + r] = v.x;
                xsT[(d4 + 1) * XPAD + r] = v.y;
                xsT[(d4 + 2) * XPAD + r] = v.z;
                xsT[(d4 + 3) * XPAD + r] = v.w;
            }
            const float4* wg = (const float4*)Wih0;
#pragma unroll
            for (int j = 0; j < 4; j++) {
                int idx = tid + 512 * j;
                float4 v = wg[idx];
                int hh = idx >> 4, d4 = (idx & 15) << 2;
                wsT[(d4 + 0) * XPAD + hh] = v.x;
                wsT[(d4 + 1) * XPAD + hh] = v.y;
                wsT[(d4 + 2) * XPAD + hh] = v.z;
                wsT[(d4 + 3) * XPAD + hh] = v.w;
            }
        }
        __syncthreads();

        if (tid < 512) {
            int tx = tid & 31, ty = tid >> 5;    // 32 col-groups x 16 row-groups
            int c0 = tx * 4, r0 = ty * 8;
            float acc[8][4];
#pragma unroll
            for (int j = 0; j < 4; j++) {
                float bb = bih0[c0 + j] + bhh0[c0 + j];
#pragma unroll
                for (int i = 0; i < 8; i++) acc[i][j] = bb;
            }
#pragma unroll 8
            for (int k = 0; k < 64; k++) {
                float4 a0 = *(const float4*)&xsT[k * XPAD + r0];
                float4 a1 = *(const float4*)&xsT[k * XPAD + r0 + 4];
                float4 b0 = *(const float4*)&wsT[k * XPAD + c0];
                float av[8] = {a0.x, a0.y, a0.z, a0.w, a1.x, a1.y, a1.z, a1.w};
                float bv[4] = {b0.x, b0.y, b0.z, b0.w};
#pragma unroll
                for (int i = 0; i < 8; i++)
#pragma unroll
                    for (int j = 0; j < 4; j++)
                        acc[i][j] = fmaf(av[i], bv[j], acc[i][j]);
            }
            float* og = g_xp0 + (size_t)row0 * HH;
#pragma unroll
            for (int i = 0; i < 8; i++)
                *(float4*)&og[(size_t)(r0 + i) * HH + c0] =
                    make_float4(acc[i][0], acc[i][1], acc[i][2], acc[i][3]);
        }
        __threadfence();
        __syncthreads();
        if (tid == 0)
            asm volatile("st.release.gpu.global.b32 [%0], %1;"
                         :: "l"(&g_xpflag[c * BB + b]), "r"(1) : "memory");
    } else {
        // -------------------------- fc role --------------------------
        __shared__ __align__(16) float wfcT[HH * 33];
        __shared__ __align__(16) float h1s[32 * HH];
        __shared__ float bfcs[OO];

        int f    = blockIdx.x - (BB + NCHUNK * BB);  // 0..8191
        int b    = (BB - 1) - (f >> 6);              // reverse batch order
        int row0 = b * TT + (f & 63) * 32;
        int L    = lengths[b];

        for (int idx = tid; idx < OO * HH; idx += 768) {
            int o = idx >> 7, k = idx & 127;
            wfcT[k * 33 + o] = Wfc[idx];
        }
        if (tid < OO) bfcs[tid] = bfc[tid];

        if (tid == 0) spin_acq(&g_scanflag[b]);
        __syncthreads();   // flag acquired -> h1 visible; smem staged

        const float4* hg = (const float4*)(g_h1 + (size_t)row0 * HH);
        for (int j = tid; j < 1024; j += 768)
            ((float4*)h1s)[j] = hg[j];
        __syncthreads();

        if (tid < 256) {
            int o  = tid & 31;
            int rg = tid >> 5;               // 8 groups x 4 rows
            int tb = row0 % TT;
#pragma unroll
            for (int i = 0; i < 4; i++) {
                int r = rg * 4 + i;
                int t = tb + r;
                float res;
                if (t < L) {
                    float acc = 0.f;
#pragma unroll
                    for (int k = 0; k < HH; k++)
                        acc = fmaf(wfcT[k * 33 + o], h1s[r * HH + k], acc);
                    res = acc + bfcs[o];
                } else {
                    res = bfcs[o];
                }
                out[(size_t)(row0 + r) * OO + o] = res;
            }
        }
    }
}

// ---------------------------------------------------------------------------
extern "C" void kernel_launch(void* const* d_in, const int* in_sizes, int n_in,
                              void* d_out, int out_size) {
    const float* x     = (const float*)d_in[0];
    const int*   len   = (const int*)  d_in[1];
    const float* Wih0  = (const float*)d_in[2];
    const float* Whh0  = (const float*)d_in[3];
    const float* bih0  = (const float*)d_in[4];
    const float* bhh0  = (const float*)d_in[5];
    const float* Wih1  = (const float*)d_in[6];
    const float* Whh1  = (const float*)d_in[7];
    const float* bih1  = (const float*)d_in[8];
    const float* bhh1  = (const float*)d_in[9];
    const float* Wfc   = (const float*)d_in[10];
    const float* bfc   = (const float*)d_in[11];
    float* out = (float*)d_out;

    init_kernel<<<1, 256>>>();

    static_assert(2 * 64 * XPAD * 4 == 67584, "smem size");
    cudaFuncSetAttribute(mega_kernel, cudaFuncAttributeMaxDynamicSharedMemorySize, 67584);
    int grid = BB + NCHUNK * BB + (BB * TT) / 32;   // 128 + 2048 + 8192
    mega_kernel<<<grid, 768, 67584>>>(x, Wih0, bih0, bhh0,
                                      Whh0, Wih1, Whh1, bih1, bhh1, len,
                                      Wfc, bfc, out);
}

// round 17
// speedup vs baseline: 1.2785x; 1.2785x over previous
#include <cuda_runtime.h>
#include <cuda_fp16.h>
#include <cstdint>

#define BB 128
#define TT 2048
#define DD 64
#define HH 128
#define OO 32
#define NCHUNK 16            // 2048 / 128 t-chunks

typedef unsigned long long ull;

// Scratch (allocation-free rule: __device__ globals)
__device__ float g_xp0[(size_t)BB * TT * HH];  // layer0 input projection
__device__ float g_h1[(size_t)BB * TT * HH];   // layer1 hidden states
__device__ int   g_scanflag[BB];               // scan-done flags
__device__ int   g_xpflag[NCHUNK * BB];        // xp chunk-ready flags [c*BB+b]

// ---------------------------------------------------------------------------
__device__ __forceinline__ float tanh_mufu(float x) {
    float t;
    asm("tanh.approx.f32 %0, %1;" : "=f"(t) : "f"(x));
    return t;
}

// 128-long fp16 dot: weights as 64 half2 in regs, vector from smem as fp16
// (16x LDS.128 broadcast). 4 chains of depth 16 (dep spacing 8cyc > lat) ->
// reduce tail is only 8 F2F + 7 FADD (was 16 F2F + 15 FADD with 8 chains).
__device__ __forceinline__ float dot128h(const __half2* w2, const __half* v) {
    __half2 a0 = __float2half2_rn(0.f);
    __half2 a1 = a0, a2 = a0, a3 = a0;
    const uint4* v4 = (const uint4*)v;          // 8 fp16 per load
#pragma unroll
    for (int j = 0; j < 16; j++) {
        uint4 p = v4[j];
        a0 = __hfma2(w2[4 * j + 0], *(const __half2*)&p.x, a0);
        a1 = __hfma2(w2[4 * j + 1], *(const __half2*)&p.y, a1);
        a2 = __hfma2(w2[4 * j + 2], *(const __half2*)&p.z, a2);
        a3 = __hfma2(w2[4 * j + 3], *(const __half2*)&p.w, a3);
    }
    float2 f0 = __half22float2(a0);
    float2 f1 = __half22float2(a1);
    float2 f2 = __half22float2(a2);
    float2 f3 = __half22float2(a3);
    return ((f0.x + f0.y) + (f1.x + f1.y)) + ((f2.x + f2.y) + (f3.x + f3.y));
}

__device__ __forceinline__ void spin_acq(const int* p) {
    int v;
    while (true) {
        asm volatile("ld.acquire.gpu.global.b32 %0, [%1];" : "=r"(v) : "l"(p) : "memory");
        if (v) break;
        __nanosleep(100);
    }
}

// ---------------------------------------------------------------------------
__global__ void init_kernel() {
    int tid = threadIdx.x;
    for (int i = tid; i < NCHUNK * BB; i += 256) g_xpflag[i] = 0;
    if (tid < BB) g_scanflag[tid] = 0;
}

// ---------------------------------------------------------------------------
// MERGED kernel: xproj + scan + fc, one launch, flag handshakes (R15 layout).
//   blocks [0,128)        : scan role (fp16 dots + xp-chunk waits)
//   blocks [128,2176)     : xproj role, chunk-major order
//   blocks [2176,10368)   : fc role, reverse batch order, spin on scan flag
#define XPAD 132
__global__ void __launch_bounds__(384, 1)
mega_kernel(const float* __restrict__ x,
            const float* __restrict__ Wih0, const float* __restrict__ bih0,
            const float* __restrict__ bhh0,
            const float* __restrict__ Whh0, const float* __restrict__ Wih1,
            const float* __restrict__ Whh1, const float* __restrict__ bih1,
            const float* __restrict__ bhh1, const int* __restrict__ lengths,
            const float* __restrict__ Wfc,  const float* __restrict__ bfc,
            float* __restrict__ out) {
    int tid = threadIdx.x;

    if (blockIdx.x < BB) {
        // ------------------------- scan role (fp16) -------------------------
        __shared__ __align__(16) __half h0buf[2][HH];
        __shared__ __align__(16) __half h1buf[2][HH];
        __shared__ __align__(16) float  p1buf[2][HH];

        int b   = blockIdx.x;
        int L   = lengths[b];
        int grp = tid >> 7;
        int row = tid & 127;
        bool isg0 = (grp == 0), isg1 = (grp == 1), isg2 = (grp == 2);

        const float* Wrow = (isg0 ? Whh0 : (isg1 ? Wih1 : Whh1)) + (size_t)row * HH;
        __half2 w2[64];
        {
            const float2* Wf2 = (const float2*)Wrow;
#pragma unroll
            for (int j = 0; j < 64; j++) {
                float2 t = Wf2[j];
                w2[j] = __floats2half2_rn(t.x, t.y);
            }
        }

        const float* xp_base = g_xp0 + (size_t)b * TT * HH + row;
        float cinit = isg1 ? (bih1[row] + bhh1[row]) : 0.f;

        if (isg0) spin_acq(&g_xpflag[b]);     // chunk 0 of this batch ready
        float xp[4];
#pragma unroll
        for (int i = 0; i < 4; i++) xp[i] = isg0 ? xp_base[(size_t)i * HH] : cinit;

        if (isg0) h0buf[1][row] = __float2half_rn(0.f);  // value -1 in buffer 1
        if (isg2) h1buf[1][row] = __float2half_rn(0.f);

        const __half* vrd[2];
        const float*  prd[2];
#pragma unroll
        for (int pa = 0; pa < 2; pa++) {
            int pb = pa ^ 1;
            vrd[pa] = isg2 ? h1buf[pb] : h0buf[pb];
            prd[pa] = &p1buf[pa][row];
        }
        __half* sth[2];
        float*  stf[2];
#pragma unroll
        for (int pa = 0; pa < 2; pa++) {
            int pb = pa ^ 1;
            sth[pa] = isg0 ? &h0buf[pa][row] : &h1buf[pa][row];  // g0/g2 targets
            stf[pa] = &p1buf[pb][row];                            // g1 target
        }
        float* h1out = g_h1 + (size_t)b * TT * HH + row;

        __syncthreads();

        int spad = ((L + 2) + 3) & ~3;
        for (int s0 = 0; s0 < spad; s0 += 4) {
            if (((s0 & 127) == 124) && isg0) {       // prefetch crosses chunk
                int c = (s0 + 7) >> 7; if (c > NCHUNK - 1) c = NCHUNK - 1;
                spin_acq(&g_xpflag[c * BB + b]);
            }
#pragma unroll
            for (int u = 0; u < 4; u++) {
                int s  = s0 + u;
                int pa = u & 1;
                float extra = *prd[pa];               // p1 value s-2 (g2 only)
                float d   = xp[u] + dot128h(w2, vrd[pa]);
                float pre = d + (isg2 ? extra : 0.f);
                float th  = tanh_mufu(pre);
                if (isg1) *stf[pa] = pre;             // p1 (fp32)
                else if (!isg2 || s >= 2)
                    *sth[pa] = __float2half_rn(th);   // h0/h1 (fp16)
                if (isg2 && (unsigned)(s - 2) < (unsigned)TT)
                    h1out[(size_t)(s - 2) * HH] = th; // fp32 for fc
                if (isg0) {                           // predicated prefetch LDG
                    int nidx = s + 4; if (nidx > TT - 1) nidx = TT - 1;
                    xp[u] = __ldg(&xp_base[(size_t)nidx * HH]);
                }
                __syncthreads();
            }
        }

        __threadfence();
        __syncthreads();
        if (tid == 0)
            asm volatile("st.release.gpu.global.b32 [%0], %1;"
                         :: "l"(&g_scanflag[b]), "r"(1) : "memory");
    } else if (blockIdx.x < BB + NCHUNK * BB) {
        // ------------------------ xproj role -------------------------
        extern __shared__ float sm[];
        float* xsT = sm;                 // [64][XPAD]
        float* wsT = sm + 64 * XPAD;     // [64][XPAD]
        int f    = blockIdx.x - BB;
        int c    = f >> 7;               // t-chunk (chunk-major order)
        int b    = f & 127;
        int row0 = b * TT + c * 128;     // 128 contiguous (b,t) rows

        if (tid < 256) {
            const float4* xg = (const float4*)(x + (size_t)row0 * DD);
#pragma unroll
            for (int j = 0; j < 8; j++) {
                int idx = tid + 256 * j;
                float4 v = xg[idx];
                int r = idx >> 4, d4 = (idx & 15) << 2;
                xsT[(d4 + 0) * XPAD + r] = v.x;
                xsT[(d4 + 1) * XPAD + r] = v.y;
                xsT[(d4 + 2) * XPAD + r] = v.z;
                xsT[(d4 + 3) * XPAD + r] = v.w;
            }
            const float4* wg = (const float4*)Wih0;
#pragma unroll
            for (int j = 0; j < 8; j++) {
                int idx = tid + 256 * j;
                float4 v = wg[idx];
                int h = idx >> 4, d4 = (idx & 15) << 2;
                wsT[(d4 + 0) * XPAD + h] = v.x;
                wsT[(d4 + 1) * XPAD + h] = v.y;
                wsT[(d4 + 2) * XPAD + h] = v.z;
                wsT[(d4 + 3) * XPAD + h] = v.w;
            }
        }
        __syncthreads();

        if (tid < 256) {
            int tx = tid & 15, ty = tid >> 4;
            int c0 = tx * 8, r0 = ty * 8;
            float acc[8][8];
#pragma unroll
            for (int j = 0; j < 8; j++) {
                float bb = bih0[c0 + j] + bhh0[c0 + j];
#pragma unroll
                for (int i = 0; i < 8; i++) acc[i][j] = bb;
            }
#pragma unroll 8
            for (int k = 0; k < 64; k++) {
                float4 a0 = *(const float4*)&xsT[k * XPAD + r0];
                float4 a1 = *(const float4*)&xsT[k * XPAD + r0 + 4];
                float4 b0 = *(const float4*)&wsT[k * XPAD + c0];
                float4 b1 = *(const float4*)&wsT[k * XPAD + c0 + 4];
                float av[8] = {a0.x, a0.y, a0.z, a0.w, a1.x, a1.y, a1.z, a1.w};
                float bv[8] = {b0.x, b0.y, b0.z, b0.w, b1.x, b1.y, b1.z, b1.w};
#pragma unroll
                for (int i = 0; i < 8; i++)
#pragma unroll
                    for (int j = 0; j < 8; j++)
                        acc[i][j] = fmaf(av[i], bv[j], acc[i][j]);
            }
            float* og = g_xp0 + (size_t)row0 * HH;
#pragma unroll
            for (int i = 0; i < 8; i++) {
                *(float4*)&og[(size_t)(r0 + i) * HH + c0] =
                    make_float4(acc[i][0], acc[i][1], acc[i][2], acc[i][3]);
                *(float4*)&og[(size_t)(r0 + i) * HH + c0 + 4] =
                    make_float4(acc[i][4], acc[i][5], acc[i][6], acc[i][7]);
            }
        }
        __threadfence();
        __syncthreads();
        if (tid == 0)
            asm volatile("st.release.gpu.global.b32 [%0], %1;"
                         :: "l"(&g_xpflag[c * BB + b]), "r"(1) : "memory");
    } else {
        // -------------------------- fc role --------------------------
        __shared__ __align__(16) float wfcT[HH * 33];
        __shared__ __align__(16) float h1s[32 * HH];
        __shared__ float bfcs[OO];

        int f    = blockIdx.x - (BB + NCHUNK * BB);  // 0..8191
        int b    = (BB - 1) - (f >> 6);              // reverse batch order
        int row0 = b * TT + (f & 63) * 32;
        int L    = lengths[b];

        for (int idx = tid; idx < OO * HH; idx += 384) {
            int o = idx >> 7, k = idx & 127;
            wfcT[k * 33 + o] = Wfc[idx];
        }
        if (tid < OO) bfcs[tid] = bfc[tid];

        if (tid == 0) spin_acq(&g_scanflag[b]);
        __syncthreads();   // flag acquired -> h1 visible; smem staged

        const float4* hg = (const float4*)(g_h1 + (size_t)row0 * HH);
        for (int j = tid; j < 1024; j += 384)
            ((float4*)h1s)[j] = hg[j];
        __syncthreads();

        if (tid < 256) {
            int o  = tid & 31;
            int rg = tid >> 5;               // 8 groups x 4 rows
            int tb = row0 % TT;
#pragma unroll
            for (int i = 0; i < 4; i++) {
                int r = rg * 4 + i;
                int t = tb + r;
                float res;
                if (t < L) {
                    float acc = 0.f;
#pragma unroll
                    for (int k = 0; k < HH; k++)
                        acc = fmaf(wfcT[k * 33 + o], h1s[r * HH + k], acc);
                    res = acc + bfcs[o];
                } else {
                    res = bfcs[o];
                }
                out[(size_t)(row0 + r) * OO + o] = res;
            }
        }
    }
}

// ---------------------------------------------------------------------------
extern "C" void kernel_launch(void* const* d_in, const int* in_sizes, int n_in,
                              void* d_out, int out_size) {
    const float* x     = (const float*)d_in[0];
    const int*   len   = (const int*)  d_in[1];
    const float* Wih0  = (const float*)d_in[2];
    const float* Whh0  = (const float*)d_in[3];
    const float* bih0  = (const float*)d_in[4];
    const float* bhh0  = (const float*)d_in[5];
    const float* Wih1  = (const float*)d_in[6];
    const float* Whh1  = (const float*)d_in[7];
    const float* bih1  = (const float*)d_in[8];
    const float* bhh1  = (const float*)d_in[9];
    const float* Wfc   = (const float*)d_in[10];
    const float* bfc   = (const float*)d_in[11];
    float* out = (float*)d_out;

    init_kernel<<<1, 256>>>();

    static_assert(2 * 64 * XPAD * 4 == 67584, "smem size");
    cudaFuncSetAttribute(mega_kernel, cudaFuncAttributeMaxDynamicSharedMemorySize, 67584);
    int grid = BB + NCHUNK * BB + (BB * TT) / 32;   // 128 + 2048 + 8192
    mega_kernel<<<grid, 384, 67584>>>(x, Wih0, bih0, bhh0,
                                      Whh0, Wih1, Whh1, bih1, bhh1, len,
                                      Wfc, bfc, out);
}